// round 14
// baseline (speedup 1.0000x reference)
#include <cuda_runtime.h>
#include <stdint.h>

// Problem constants (fixed by the dataset)
#define NN 100000      // nodes
#define F0 128
#define F1 64
#define F2 40

// ---------------- scratch (static device globals; allocation-free) ----------
__device__ __align__(16) float g_h1s [NN * F1];   // (x @ W1) * invsqrt[row]
__device__ __align__(16) float g_agg1[NN * F1];   // sum of h1s[src] per dst
__device__ __align__(16) float g_h2s [NN * F2];   // (out1 @ W2) * invsqrt[row]
__device__ __align__(16) float g_agg2[NN * F2];   // sum of h2s[src] per dst
__device__ int   g_deg[NN];

// ---------------- helpers ---------------------------------------------------
__device__ __forceinline__ void red_add_v4(float* addr, float4 v) {
    asm volatile("red.global.add.v4.f32 [%0], {%1, %2, %3, %4};"
                 :: "l"(addr), "f"(v.x), "f"(v.y), "f"(v.z), "f"(v.w)
                 : "memory");
}
__device__ __forceinline__ float inv_sqrt_deg(int node) {
    return rsqrtf((float)(g_deg[node] + 1));
}

// ---------------- kernels ---------------------------------------------------

// 1st launch: zero deg counters (agg zeroing folded into gemm1/fuse2).
__global__ void zero_kernel() {
    int i = blockIdx.x * blockDim.x + threadIdx.x;
    if (i < NN) g_deg[i] = 0;
}

// 2nd launch: degree histogram over dst; 2 edges per thread.
__global__ void deg_kernel(const int* __restrict__ dst, int E) {
    int i = (blockIdx.x * blockDim.x + threadIdx.x) * 2;
    if (i + 1 < E) {
        int2 d = *reinterpret_cast<const int2*>(dst + i);
        atomicAdd(&g_deg[d.x], 1);
        atomicAdd(&g_deg[d.y], 1);
    } else if (i < E) {
        atomicAdd(&g_deg[dst[i]], 1);
    }
}

// 3rd launch: h1s = (x @ W1) * rsqrt(deg+1)  (100000x128 @ 128x64), fp32.
// v3: 256 threads, block tile 128 rows x 64 cols, 8x4 micro-tile (32 acc regs),
// k-chunks of 32. tx 0..15 -> cols tx*4..+3; ty 0..15 -> rows ty*4..+3 and
// 64+ty*4..+3. Per k: 2 LDS.128 (x) + 1 LDS.128 (w) per 32 FMA; ~70 regs
// -> ~3 CTAs/SM, ~50% occupancy (between the 4x4@46% and 8x8@17% configs).
// Epilogue also zeros the matching agg1 slots.
__global__ __launch_bounds__(256) void gemm1_kernel(const float* __restrict__ x,
                                                    const float* __restrict__ W1) {
    __shared__ float sX[32][132];           // [k_local][row 0..127], padded pitch
    __shared__ float sW[32 * F1];           // [k_local][col], 8 KB
    int tid = threadIdx.x;
    int row0 = blockIdx.x * 128;

    int tx = tid & 15;                      // col group: cols tx*4..+3
    int ty = tid >> 4;                      // row groups: ty*4 and 64+ty*4

    float acc[8][4];
    #pragma unroll
    for (int r = 0; r < 8; ++r)
        #pragma unroll
        for (int c = 0; c < 4; ++c) acc[r][c] = 0.f;

    #pragma unroll
    for (int kc = 0; kc < 4; ++kc) {
        int k0 = kc * 32;

        // W chunk: 32 k-rows x 64 cols = 512 float4; 2 per thread
        const float4* w4g = reinterpret_cast<const float4*>(W1 + k0 * F1);
        #pragma unroll
        for (int i = 0; i < 2; ++i)
            reinterpret_cast<float4*>(sW)[tid + i * 256] = w4g[tid + i * 256];

        // x chunk: 128 rows x 32 k = 1024 float4; 4 per thread, transposed
        #pragma unroll
        for (int i = 0; i < 4; ++i) {
            int idx = tid + i * 256;        // 0..1023
            int r   = idx >> 3;             // 0..127
            int k4  = idx & 7;              // 0..7 (float4 along k)
            int rr = row0 + r; if (rr >= NN) rr = NN - 1;
            float4 v = reinterpret_cast<const float4*>(
                           x + (size_t)rr * F0 + k0)[k4];
            sX[k4 * 4 + 0][r] = v.x;
            sX[k4 * 4 + 1][r] = v.y;
            sX[k4 * 4 + 2][r] = v.z;
            sX[k4 * 4 + 3][r] = v.w;
        }
        __syncthreads();

        #pragma unroll 4
        for (int k = 0; k < 32; ++k) {
            float4 xv0 = *reinterpret_cast<const float4*>(&sX[k][ty * 4]);
            float4 xv1 = *reinterpret_cast<const float4*>(&sX[k][64 + ty * 4]);
            float4 wv  = *reinterpret_cast<const float4*>(&sW[k * F1 + tx * 4]);
            float xa[8] = {xv0.x, xv0.y, xv0.z, xv0.w, xv1.x, xv1.y, xv1.z, xv1.w};
            float wa[4] = {wv.x, wv.y, wv.z, wv.w};
            #pragma unroll
            for (int r = 0; r < 8; ++r)
                #pragma unroll
                for (int c = 0; c < 4; ++c)
                    acc[r][c] = fmaf(xa[r], wa[c], acc[r][c]);
        }
        __syncthreads();
    }

    float4 z = make_float4(0.f, 0.f, 0.f, 0.f);
    #pragma unroll
    for (int r = 0; r < 8; ++r) {
        int rr = row0 + ((r < 4) ? (ty * 4 + r) : (64 + ty * 4 + r - 4));
        if (rr < NN) {
            float sc = inv_sqrt_deg(rr);
            float* hb = g_h1s  + (size_t)rr * F1;
            float* ab = g_agg1 + (size_t)rr * F1;
            *reinterpret_cast<float4*>(hb + tx * 4) =
                make_float4(acc[r][0]*sc, acc[r][1]*sc, acc[r][2]*sc, acc[r][3]*sc);
            *reinterpret_cast<float4*>(ab + tx * 4) = z;
        }
    }
}

// 4th launch (PROFILED): layer-1 scatter agg1[dst] += h1s[src].
// 8 threads/edge, split-half chunks (verified R13 kernel, unchanged).
__global__ __launch_bounds__(256) void scatter1_kernel(const int* __restrict__ src,
                                                       const int* __restrict__ dst, int E) {
    int i = blockIdx.x * blockDim.x + threadIdx.x;
    int total = E * 8;
    if (i >= total) return;
    int e = i >> 3;
    int c = i & 7;                 // float4 index in line 0; c+8 in line 1
    int s = __ldg(src + e);
    int d = __ldg(dst + e);
    const float4* hp = reinterpret_cast<const float4*>(g_h1s + (size_t)s * F1) + c;
    float*        ap = g_agg1 + (size_t)d * F1 + c * 4;
    float4 v0 = hp[0];             // float4[c]
    float4 v1 = hp[8];             // float4[c+8]
    red_add_v4(ap,      v0);
    red_add_v4(ap + 32, v1);       // +8 float4 = +32 floats
}

// out1 = relu(inv_d * (agg1 + h1s));  h2s = (out1 @ W2) * inv_d.
// Also zeros this row's agg2 slots (runs before scatter2).
__global__ __launch_bounds__(256) void fuse2_kernel(const float* __restrict__ W2) {
    __shared__ float sW[F1 * F2];
    int tid = threadIdx.x;
    for (int i = tid; i < F1 * F2; i += 256) sW[i] = W2[i];
    __syncthreads();

    int row = blockIdx.x * 256 + tid;
    if (row >= NN) return;

    float inv_d = inv_sqrt_deg(row);

    float o[F1];
    const float4* ag = reinterpret_cast<const float4*>(g_agg1 + (size_t)row * F1);
    const float4* hr = reinterpret_cast<const float4*>(g_h1s  + (size_t)row * F1);
    #pragma unroll
    for (int j = 0; j < F1 / 4; ++j) {
        float4 a = ag[j];
        float4 h = hr[j];
        o[4*j+0] = fmaxf(inv_d * (a.x + h.x), 0.f);
        o[4*j+1] = fmaxf(inv_d * (a.y + h.y), 0.f);
        o[4*j+2] = fmaxf(inv_d * (a.z + h.z), 0.f);
        o[4*j+3] = fmaxf(inv_d * (a.w + h.w), 0.f);
    }

    float acc[F2];
    #pragma unroll
    for (int j = 0; j < F2; ++j) acc[j] = 0.f;

    #pragma unroll 4
    for (int k = 0; k < F1; ++k) {
        float ov = o[k];
        const float4* w4 = reinterpret_cast<const float4*>(sW + k * F2);
        #pragma unroll
        for (int j = 0; j < F2 / 4; ++j) {
            float4 w = w4[j];
            acc[4*j+0] = fmaf(ov, w.x, acc[4*j+0]);
            acc[4*j+1] = fmaf(ov, w.y, acc[4*j+1]);
            acc[4*j+2] = fmaf(ov, w.z, acc[4*j+2]);
            acc[4*j+3] = fmaf(ov, w.w, acc[4*j+3]);
        }
    }
    float4* out = reinterpret_cast<float4*>(g_h2s + (size_t)row * F2);
    float4* az  = reinterpret_cast<float4*>(g_agg2 + (size_t)row * F2);
    float4 z = make_float4(0.f, 0.f, 0.f, 0.f);
    #pragma unroll
    for (int j = 0; j < F2 / 4; ++j) {
        out[j] = make_float4(acc[4*j]*inv_d, acc[4*j+1]*inv_d,
                             acc[4*j+2]*inv_d, acc[4*j+3]*inv_d);
        az[j] = z;
    }
}

// Layer-2 scatter: agg2[dst] += h2s[src].  5 threads/edge, split-half chunks
// (verified R13 kernel, unchanged).
__global__ __launch_bounds__(256) void scatter2_kernel(const int* __restrict__ src,
                                                       const int* __restrict__ dst, int E) {
    int i = blockIdx.x * blockDim.x + threadIdx.x;
    int total = E * 5;
    if (i >= total) return;
    int e = i / 5;
    int c = i - e * 5;             // 0..4
    int s = __ldg(src + e);
    int d = __ldg(dst + e);
    const float4* hp = reinterpret_cast<const float4*>(g_h2s + (size_t)s * F2) + c;
    float*        ap = g_agg2 + (size_t)d * F2 + c * 4;
    float4 v0 = hp[0];             // float4[c]
    float4 v1 = hp[5];             // float4[c+5]
    red_add_v4(ap,      v0);
    red_add_v4(ap + 20, v1);       // +5 float4 = +20 floats
}

// out = relu(inv_d * (agg2 + h2s))
__global__ __launch_bounds__(256) void final_kernel(float* __restrict__ out) {
    int i = blockIdx.x * blockDim.x + threadIdx.x;
    const int total = NN * (F2 / 4);
    if (i >= total) return;
    int node = i / 10;
    float inv_d = inv_sqrt_deg(node);
    float4 a = reinterpret_cast<const float4*>(g_agg2)[i];
    float4 h = reinterpret_cast<const float4*>(g_h2s)[i];
    float4 r;
    r.x = fmaxf(inv_d * (a.x + h.x), 0.f);
    r.y = fmaxf(inv_d * (a.y + h.y), 0.f);
    r.z = fmaxf(inv_d * (a.z + h.z), 0.f);
    r.w = fmaxf(inv_d * (a.w + h.w), 0.f);
    reinterpret_cast<float4*>(out)[i] = r;
}

// ---------------- launch ----------------------------------------------------
extern "C" void kernel_launch(void* const* d_in, const int* in_sizes, int n_in,
                              void* d_out, int out_size) {
    const float* x  = (const float*)d_in[0];   // [N,128]
    const int*   ei = (const int*)  d_in[1];   // [2,E]
    const float* W1 = (const float*)d_in[2];   // [128,64]
    const float* W2 = (const float*)d_in[3];   // [64,40]
    float* out = (float*)d_out;

    int E = in_sizes[1] / 2;
    const int* src = ei;
    const int* dst = ei + E;

    // 1. zero deg
    zero_kernel<<<(NN + 255) / 256, 256>>>();
    // 2. degree histogram (2 edges/thread)
    deg_kernel<<<(E/2 + 255) / 256, 256>>>(dst, E);
    // 3. h1s = (x @ W1) * rsqrt(deg+1)  (8x4 micro-tile; also zeros agg1)
    gemm1_kernel<<<(NN + 127) / 128, 256>>>(x, W1);
    // 4. layer-1 edge scatter (split-half lines)  <-- profiled launch
    scatter1_kernel<<<(E * 8 + 255) / 256, 256>>>(src, dst, E);
    // 5. relu + self + GEMM2 -> h2s (also zeros agg2)
    fuse2_kernel<<<(NN + 255) / 256, 256>>>(W2);
    // 6. layer-2 edge scatter (split-half)
    scatter2_kernel<<<(E * 5 + 255) / 256, 256>>>(src, dst, E);
    // 7. final relu -> d_out
    final_kernel<<<(NN * (F2/4) + 255) / 256, 256>>>(out);
}

// round 15
// speedup vs baseline: 1.0241x; 1.0241x over previous
#include <cuda_runtime.h>
#include <stdint.h>

// Problem constants (fixed by the dataset)
#define NN 100000      // nodes
#define F0 128
#define F1 64
#define F2 40

// ---------------- scratch (static device globals; allocation-free) ----------
__device__ __align__(16) float g_h1s [NN * F1];   // (x @ W1) * invsqrt[row]
__device__ __align__(16) float g_agg1[NN * F1];   // h1s[d] + sum of h1s[src]
__device__ __align__(16) float g_h2s [NN * F2];   // (out1 @ W2) * invsqrt[row]
__device__ __align__(16) float g_agg2[NN * F2];   // h2s[d] + sum of h2s[src]
__device__ int   g_deg[NN];

// ---------------- helpers ---------------------------------------------------
__device__ __forceinline__ void red_add_v4(float* addr, float4 v) {
    asm volatile("red.global.add.v4.f32 [%0], {%1, %2, %3, %4};"
                 :: "l"(addr), "f"(v.x), "f"(v.y), "f"(v.z), "f"(v.w)
                 : "memory");
}
__device__ __forceinline__ float inv_sqrt_deg(int node) {
    return rsqrtf((float)(g_deg[node] + 1));
}

// ---------------- kernels ---------------------------------------------------

// 1st launch: zero deg counters.
__global__ void zero_kernel() {
    int i = blockIdx.x * blockDim.x + threadIdx.x;
    if (i < NN) g_deg[i] = 0;
}

// 2nd launch: degree histogram over dst; 2 edges per thread.
__global__ void deg_kernel(const int* __restrict__ dst, int E) {
    int i = (blockIdx.x * blockDim.x + threadIdx.x) * 2;
    if (i + 1 < E) {
        int2 d = *reinterpret_cast<const int2*>(dst + i);
        atomicAdd(&g_deg[d.x], 1);
        atomicAdd(&g_deg[d.y], 1);
    } else if (i < E) {
        atomicAdd(&g_deg[dst[i]], 1);
    }
}

// 3rd launch: h1s = (x @ W1) * rsqrt(deg+1)  (8x4 micro-tile, verified R14).
// Epilogue stores h1s into BOTH h1s and agg1 (self-term pre-seeded; fuse2
// then needs only agg1 -> saves 25.6 MB of reads downstream).
__global__ __launch_bounds__(256) void gemm1_kernel(const float* __restrict__ x,
                                                    const float* __restrict__ W1) {
    __shared__ float sX[32][132];           // [k_local][row 0..127], padded pitch
    __shared__ float sW[32 * F1];           // [k_local][col], 8 KB
    int tid = threadIdx.x;
    int row0 = blockIdx.x * 128;

    int tx = tid & 15;                      // col group: cols tx*4..+3
    int ty = tid >> 4;                      // row groups: ty*4 and 64+ty*4

    float acc[8][4];
    #pragma unroll
    for (int r = 0; r < 8; ++r)
        #pragma unroll
        for (int c = 0; c < 4; ++c) acc[r][c] = 0.f;

    #pragma unroll
    for (int kc = 0; kc < 4; ++kc) {
        int k0 = kc * 32;

        const float4* w4g = reinterpret_cast<const float4*>(W1 + k0 * F1);
        #pragma unroll
        for (int i = 0; i < 2; ++i)
            reinterpret_cast<float4*>(sW)[tid + i * 256] = w4g[tid + i * 256];

        #pragma unroll
        for (int i = 0; i < 4; ++i) {
            int idx = tid + i * 256;        // 0..1023
            int r   = idx >> 3;             // 0..127
            int k4  = idx & 7;              // 0..7 (float4 along k)
            int rr = row0 + r; if (rr >= NN) rr = NN - 1;
            float4 v = reinterpret_cast<const float4*>(
                           x + (size_t)rr * F0 + k0)[k4];
            sX[k4 * 4 + 0][r] = v.x;
            sX[k4 * 4 + 1][r] = v.y;
            sX[k4 * 4 + 2][r] = v.z;
            sX[k4 * 4 + 3][r] = v.w;
        }
        __syncthreads();

        #pragma unroll 4
        for (int k = 0; k < 32; ++k) {
            float4 xv0 = *reinterpret_cast<const float4*>(&sX[k][ty * 4]);
            float4 xv1 = *reinterpret_cast<const float4*>(&sX[k][64 + ty * 4]);
            float4 wv  = *reinterpret_cast<const float4*>(&sW[k * F1 + tx * 4]);
            float xa[8] = {xv0.x, xv0.y, xv0.z, xv0.w, xv1.x, xv1.y, xv1.z, xv1.w};
            float wa[4] = {wv.x, wv.y, wv.z, wv.w};
            #pragma unroll
            for (int r = 0; r < 8; ++r)
                #pragma unroll
                for (int c = 0; c < 4; ++c)
                    acc[r][c] = fmaf(xa[r], wa[c], acc[r][c]);
        }
        __syncthreads();
    }

    #pragma unroll
    for (int r = 0; r < 8; ++r) {
        int rr = row0 + ((r < 4) ? (ty * 4 + r) : (64 + ty * 4 + r - 4));
        if (rr < NN) {
            float sc = inv_sqrt_deg(rr);
            float4 hv = make_float4(acc[r][0]*sc, acc[r][1]*sc,
                                    acc[r][2]*sc, acc[r][3]*sc);
            *reinterpret_cast<float4*>(g_h1s  + (size_t)rr * F1 + tx * 4) = hv;
            *reinterpret_cast<float4*>(g_agg1 + (size_t)rr * F1 + tx * 4) = hv;
        }
    }
}

// 4th launch (PROFILED): layer-1 scatter agg1[dst] += h1s[src].
// 8 threads/edge, split-half chunks (verified R13 kernel, unchanged).
__global__ __launch_bounds__(256) void scatter1_kernel(const int* __restrict__ src,
                                                       const int* __restrict__ dst, int E) {
    int i = blockIdx.x * blockDim.x + threadIdx.x;
    int total = E * 8;
    if (i >= total) return;
    int e = i >> 3;
    int c = i & 7;                 // float4 index in line 0; c+8 in line 1
    int s = __ldg(src + e);
    int d = __ldg(dst + e);
    const float4* hp = reinterpret_cast<const float4*>(g_h1s + (size_t)s * F1) + c;
    float*        ap = g_agg1 + (size_t)d * F1 + c * 4;
    float4 v0 = hp[0];             // float4[c]
    float4 v1 = hp[8];             // float4[c+8]
    red_add_v4(ap,      v0);
    red_add_v4(ap + 32, v1);       // +8 float4 = +32 floats
}

// out1 = relu(inv_d * agg1)  (agg1 already includes self term).
// h2s = (out1 @ W2) * inv_d; epilogue seeds agg2 with h2s (self term).
__global__ __launch_bounds__(256) void fuse2_kernel(const float* __restrict__ W2) {
    __shared__ float sW[F1 * F2];
    int tid = threadIdx.x;
    for (int i = tid; i < F1 * F2; i += 256) sW[i] = W2[i];
    __syncthreads();

    int row = blockIdx.x * 256 + tid;
    if (row >= NN) return;

    float inv_d = inv_sqrt_deg(row);

    float o[F1];
    const float4* ag = reinterpret_cast<const float4*>(g_agg1 + (size_t)row * F1);
    #pragma unroll
    for (int j = 0; j < F1 / 4; ++j) {
        float4 a = ag[j];
        o[4*j+0] = fmaxf(inv_d * a.x, 0.f);
        o[4*j+1] = fmaxf(inv_d * a.y, 0.f);
        o[4*j+2] = fmaxf(inv_d * a.z, 0.f);
        o[4*j+3] = fmaxf(inv_d * a.w, 0.f);
    }

    float acc[F2];
    #pragma unroll
    for (int j = 0; j < F2; ++j) acc[j] = 0.f;

    #pragma unroll 4
    for (int k = 0; k < F1; ++k) {
        float ov = o[k];
        const float4* w4 = reinterpret_cast<const float4*>(sW + k * F2);
        #pragma unroll
        for (int j = 0; j < F2 / 4; ++j) {
            float4 w = w4[j];
            acc[4*j+0] = fmaf(ov, w.x, acc[4*j+0]);
            acc[4*j+1] = fmaf(ov, w.y, acc[4*j+1]);
            acc[4*j+2] = fmaf(ov, w.z, acc[4*j+2]);
            acc[4*j+3] = fmaf(ov, w.w, acc[4*j+3]);
        }
    }
    float4* out = reinterpret_cast<float4*>(g_h2s + (size_t)row * F2);
    float4* az  = reinterpret_cast<float4*>(g_agg2 + (size_t)row * F2);
    #pragma unroll
    for (int j = 0; j < F2 / 4; ++j) {
        float4 hv = make_float4(acc[4*j]*inv_d, acc[4*j+1]*inv_d,
                                acc[4*j+2]*inv_d, acc[4*j+3]*inv_d);
        out[j] = hv;
        az[j]  = hv;               // seed agg2 with self term
    }
}

// Layer-2 scatter: agg2[dst] += h2s[src].  5 threads/edge, split-half chunks
// (verified R13 kernel, unchanged).
__global__ __launch_bounds__(256) void scatter2_kernel(const int* __restrict__ src,
                                                       const int* __restrict__ dst, int E) {
    int i = blockIdx.x * blockDim.x + threadIdx.x;
    int total = E * 5;
    if (i >= total) return;
    int e = i / 5;
    int c = i - e * 5;             // 0..4
    int s = __ldg(src + e);
    int d = __ldg(dst + e);
    const float4* hp = reinterpret_cast<const float4*>(g_h2s + (size_t)s * F2) + c;
    float*        ap = g_agg2 + (size_t)d * F2 + c * 4;
    float4 v0 = hp[0];             // float4[c]
    float4 v1 = hp[5];             // float4[c+5]
    red_add_v4(ap,      v0);
    red_add_v4(ap + 20, v1);       // +5 float4 = +20 floats
}

// out = relu(inv_d * agg2)  (agg2 already includes self term)
__global__ __launch_bounds__(256) void final_kernel(float* __restrict__ out) {
    int i = blockIdx.x * blockDim.x + threadIdx.x;
    const int total = NN * (F2 / 4);
    if (i >= total) return;
    int node = i / 10;
    float inv_d = inv_sqrt_deg(node);
    float4 a = reinterpret_cast<const float4*>(g_agg2)[i];
    float4 r;
    r.x = fmaxf(inv_d * a.x, 0.f);
    r.y = fmaxf(inv_d * a.y, 0.f);
    r.z = fmaxf(inv_d * a.z, 0.f);
    r.w = fmaxf(inv_d * a.w, 0.f);
    reinterpret_cast<float4*>(out)[i] = r;
}

// ---------------- launch ----------------------------------------------------
extern "C" void kernel_launch(void* const* d_in, const int* in_sizes, int n_in,
                              void* d_out, int out_size) {
    const float* x  = (const float*)d_in[0];   // [N,128]
    const int*   ei = (const int*)  d_in[1];   // [2,E]
    const float* W1 = (const float*)d_in[2];   // [128,64]
    const float* W2 = (const float*)d_in[3];   // [64,40]
    float* out = (float*)d_out;

    int E = in_sizes[1] / 2;
    const int* src = ei;
    const int* dst = ei + E;

    // 1. zero deg
    zero_kernel<<<(NN + 255) / 256, 256>>>();
    // 2. degree histogram (2 edges/thread)
    deg_kernel<<<(E/2 + 255) / 256, 256>>>(dst, E);
    // 3. h1s = (x @ W1) * rsqrt(deg+1); agg1 seeded with self term
    gemm1_kernel<<<(NN + 127) / 128, 256>>>(x, W1);
    // 4. layer-1 edge scatter (split-half lines)  <-- profiled launch
    scatter1_kernel<<<(E * 8 + 255) / 256, 256>>>(src, dst, E);
    // 5. relu + GEMM2 -> h2s; agg2 seeded with self term
    fuse2_kernel<<<(NN + 255) / 256, 256>>>(W2);
    // 6. layer-2 edge scatter (split-half)
    scatter2_kernel<<<(E * 5 + 255) / 256, 256>>>(src, dst, E);
    // 7. final relu -> d_out
    final_kernel<<<(NN * (F2/4) + 255) / 256, 256>>>(out);
}

// round 16
// speedup vs baseline: 1.0243x; 1.0001x over previous
#include <cuda_runtime.h>
#include <stdint.h>

// Problem constants (fixed by the dataset)
#define NN 100000      // nodes
#define F0 128
#define F1 64
#define F2 40

// ---------------- scratch (static device globals; allocation-free) ----------
__device__ __align__(16) float g_h1s [NN * F1];   // (x @ W1) * invsqrt[row]
__device__ __align__(16) float g_agg1[NN * F1];   // h1s[d] + sum of h1s[src]
__device__ __align__(16) float g_h2s [NN * F2];   // (out1 @ W2) * invsqrt[row]
__device__ __align__(16) float g_agg2[NN * F2];   // h2s[d] + sum of h2s[src]
__device__ int   g_deg[NN];

// ---------------- helpers ---------------------------------------------------
__device__ __forceinline__ void red_add_v4(float* addr, float4 v) {
    asm volatile("red.global.add.v4.f32 [%0], {%1, %2, %3, %4};"
                 :: "l"(addr), "f"(v.x), "f"(v.y), "f"(v.z), "f"(v.w)
                 : "memory");
}
__device__ __forceinline__ float inv_sqrt_deg(int node) {
    return rsqrtf((float)(g_deg[node] + 1));
}

// ---------------- kernels ---------------------------------------------------

// 1st launch: zero deg counters.
__global__ void zero_kernel() {
    int i = blockIdx.x * blockDim.x + threadIdx.x;
    if (i < NN) g_deg[i] = 0;
}

// 2nd launch: degree histogram over dst; 4 edges per thread (int4 load, 4
// independent atomics in flight -> hides L2 atomic latency).
__global__ void deg_kernel(const int* __restrict__ dst, int E) {
    int i = (blockIdx.x * blockDim.x + threadIdx.x) * 4;
    if (i + 3 < E) {
        int4 d = *reinterpret_cast<const int4*>(dst + i);
        atomicAdd(&g_deg[d.x], 1);
        atomicAdd(&g_deg[d.y], 1);
        atomicAdd(&g_deg[d.z], 1);
        atomicAdd(&g_deg[d.w], 1);
    } else {
        for (; i < E; ++i) atomicAdd(&g_deg[dst[i]], 1);
    }
}

// 3rd launch: h1s = (x @ W1) * rsqrt(deg+1)  (8x4 micro-tile, k-chunks of 32)
// with REGISTER SOFTWARE PIPELINING: chunk kc+1's x/W global loads are issued
// before chunk kc's FMA loop, so DRAM latency overlaps compute instead of
// being exposed at each __syncthreads() boundary.
// Epilogue stores h1s into BOTH h1s and agg1 (self-term pre-seeded).
__global__ __launch_bounds__(256) void gemm1_kernel(const float* __restrict__ x,
                                                    const float* __restrict__ W1) {
    __shared__ float sX[32][132];           // [k_local][row 0..127], padded pitch
    __shared__ float sW[32 * F1];           // [k_local][col], 8 KB
    int tid = threadIdx.x;
    int row0 = blockIdx.x * 128;

    int tx = tid & 15;                      // col group: cols tx*4..+3
    int ty = tid >> 4;                      // row groups: ty*4 and 64+ty*4

    // per-thread load assignments (fixed across chunks)
    int xr[4], xk[4];
    #pragma unroll
    for (int i = 0; i < 4; ++i) {
        int idx = tid + i * 256;            // 0..1023
        int r   = idx >> 3;                 // 0..127
        xk[i]   = idx & 7;                  // float4 index along k-chunk
        int rr = row0 + r; if (rr >= NN) rr = NN - 1;
        xr[i] = rr;
    }

    float acc[8][4];
    #pragma unroll
    for (int r = 0; r < 8; ++r)
        #pragma unroll
        for (int c = 0; c < 4; ++c) acc[r][c] = 0.f;

    // prefetch registers
    float4 px[4], pw[2];

    // load chunk 0
    #pragma unroll
    for (int i = 0; i < 4; ++i)
        px[i] = reinterpret_cast<const float4*>(x + (size_t)xr[i] * F0)[xk[i]];
    #pragma unroll
    for (int i = 0; i < 2; ++i)
        pw[i] = reinterpret_cast<const float4*>(W1)[tid + i * 256];

    #pragma unroll
    for (int kc = 0; kc < 4; ++kc) {
        // store prefetched chunk kc into smem
        #pragma unroll
        for (int i = 0; i < 4; ++i) {
            int idx = tid + i * 256;
            int r   = idx >> 3;
            int k4  = idx & 7;
            sX[k4 * 4 + 0][r] = px[i].x;
            sX[k4 * 4 + 1][r] = px[i].y;
            sX[k4 * 4 + 2][r] = px[i].z;
            sX[k4 * 4 + 3][r] = px[i].w;
        }
        #pragma unroll
        for (int i = 0; i < 2; ++i)
            reinterpret_cast<float4*>(sW)[tid + i * 256] = pw[i];
        __syncthreads();

        // issue chunk kc+1 loads (in flight during the FMA loop below)
        if (kc < 3) {
            int k0n = (kc + 1) * 32;
            #pragma unroll
            for (int i = 0; i < 4; ++i)
                px[i] = reinterpret_cast<const float4*>(
                            x + (size_t)xr[i] * F0 + k0n)[xk[i]];
            #pragma unroll
            for (int i = 0; i < 2; ++i)
                pw[i] = reinterpret_cast<const float4*>(
                            W1 + k0n * F1)[tid + i * 256];
        }

        #pragma unroll 4
        for (int k = 0; k < 32; ++k) {
            float4 xv0 = *reinterpret_cast<const float4*>(&sX[k][ty * 4]);
            float4 xv1 = *reinterpret_cast<const float4*>(&sX[k][64 + ty * 4]);
            float4 wv  = *reinterpret_cast<const float4*>(&sW[k * F1 + tx * 4]);
            float xa[8] = {xv0.x, xv0.y, xv0.z, xv0.w, xv1.x, xv1.y, xv1.z, xv1.w};
            float wa[4] = {wv.x, wv.y, wv.z, wv.w};
            #pragma unroll
            for (int r = 0; r < 8; ++r)
                #pragma unroll
                for (int c = 0; c < 4; ++c)
                    acc[r][c] = fmaf(xa[r], wa[c], acc[r][c]);
        }
        __syncthreads();
    }

    #pragma unroll
    for (int r = 0; r < 8; ++r) {
        int rr = row0 + ((r < 4) ? (ty * 4 + r) : (64 + ty * 4 + r - 4));
        if (rr < NN) {
            float sc = inv_sqrt_deg(rr);
            float4 hv = make_float4(acc[r][0]*sc, acc[r][1]*sc,
                                    acc[r][2]*sc, acc[r][3]*sc);
            *reinterpret_cast<float4*>(g_h1s  + (size_t)rr * F1 + tx * 4) = hv;
            *reinterpret_cast<float4*>(g_agg1 + (size_t)rr * F1 + tx * 4) = hv;
        }
    }
}

// 4th launch (PROFILED): layer-1 scatter agg1[dst] += h1s[src].
// 8 threads/edge, split-half chunks (verified R13 kernel, unchanged).
__global__ __launch_bounds__(256) void scatter1_kernel(const int* __restrict__ src,
                                                       const int* __restrict__ dst, int E) {
    int i = blockIdx.x * blockDim.x + threadIdx.x;
    int total = E * 8;
    if (i >= total) return;
    int e = i >> 3;
    int c = i & 7;                 // float4 index in line 0; c+8 in line 1
    int s = __ldg(src + e);
    int d = __ldg(dst + e);
    const float4* hp = reinterpret_cast<const float4*>(g_h1s + (size_t)s * F1) + c;
    float*        ap = g_agg1 + (size_t)d * F1 + c * 4;
    float4 v0 = hp[0];             // float4[c]
    float4 v1 = hp[8];             // float4[c+8]
    red_add_v4(ap,      v0);
    red_add_v4(ap + 32, v1);       // +8 float4 = +32 floats
}

// out1 = relu(inv_d * agg1)  (agg1 already includes self term).
// h2s = (out1 @ W2) * inv_d; epilogue seeds agg2 with h2s (self term).
__global__ __launch_bounds__(256) void fuse2_kernel(const float* __restrict__ W2) {
    __shared__ float sW[F1 * F2];
    int tid = threadIdx.x;
    for (int i = tid; i < F1 * F2; i += 256) sW[i] = W2[i];
    __syncthreads();

    int row = blockIdx.x * 256 + tid;
    if (row >= NN) return;

    float inv_d = inv_sqrt_deg(row);

    float o[F1];
    const float4* ag = reinterpret_cast<const float4*>(g_agg1 + (size_t)row * F1);
    #pragma unroll
    for (int j = 0; j < F1 / 4; ++j) {
        float4 a = ag[j];
        o[4*j+0] = fmaxf(inv_d * a.x, 0.f);
        o[4*j+1] = fmaxf(inv_d * a.y, 0.f);
        o[4*j+2] = fmaxf(inv_d * a.z, 0.f);
        o[4*j+3] = fmaxf(inv_d * a.w, 0.f);
    }

    float acc[F2];
    #pragma unroll
    for (int j = 0; j < F2; ++j) acc[j] = 0.f;

    #pragma unroll 4
    for (int k = 0; k < F1; ++k) {
        float ov = o[k];
        const float4* w4 = reinterpret_cast<const float4*>(sW + k * F2);
        #pragma unroll
        for (int j = 0; j < F2 / 4; ++j) {
            float4 w = w4[j];
            acc[4*j+0] = fmaf(ov, w.x, acc[4*j+0]);
            acc[4*j+1] = fmaf(ov, w.y, acc[4*j+1]);
            acc[4*j+2] = fmaf(ov, w.z, acc[4*j+2]);
            acc[4*j+3] = fmaf(ov, w.w, acc[4*j+3]);
        }
    }
    float4* out = reinterpret_cast<float4*>(g_h2s + (size_t)row * F2);
    float4* az  = reinterpret_cast<float4*>(g_agg2 + (size_t)row * F2);
    #pragma unroll
    for (int j = 0; j < F2 / 4; ++j) {
        float4 hv = make_float4(acc[4*j]*inv_d, acc[4*j+1]*inv_d,
                                acc[4*j+2]*inv_d, acc[4*j+3]*inv_d);
        out[j] = hv;
        az[j]  = hv;               // seed agg2 with self term
    }
}

// Layer-2 scatter: agg2[dst] += h2s[src].  5 threads/edge, split-half chunks
// (verified R13 kernel, unchanged).
__global__ __launch_bounds__(256) void scatter2_kernel(const int* __restrict__ src,
                                                       const int* __restrict__ dst, int E) {
    int i = blockIdx.x * blockDim.x + threadIdx.x;
    int total = E * 5;
    if (i >= total) return;
    int e = i / 5;
    int c = i - e * 5;             // 0..4
    int s = __ldg(src + e);
    int d = __ldg(dst + e);
    const float4* hp = reinterpret_cast<const float4*>(g_h2s + (size_t)s * F2) + c;
    float*        ap = g_agg2 + (size_t)d * F2 + c * 4;
    float4 v0 = hp[0];             // float4[c]
    float4 v1 = hp[5];             // float4[c+5]
    red_add_v4(ap,      v0);
    red_add_v4(ap + 20, v1);       // +5 float4 = +20 floats
}

// out = relu(inv_d * agg2)  (agg2 already includes self term)
__global__ __launch_bounds__(256) void final_kernel(float* __restrict__ out) {
    int i = blockIdx.x * blockDim.x + threadIdx.x;
    const int total = NN * (F2 / 4);
    if (i >= total) return;
    int node = i / 10;
    float inv_d = inv_sqrt_deg(node);
    float4 a = reinterpret_cast<const float4*>(g_agg2)[i];
    float4 r;
    r.x = fmaxf(inv_d * a.x, 0.f);
    r.y = fmaxf(inv_d * a.y, 0.f);
    r.z = fmaxf(inv_d * a.z, 0.f);
    r.w = fmaxf(inv_d * a.w, 0.f);
    reinterpret_cast<float4*>(out)[i] = r;
}

// ---------------- launch ----------------------------------------------------
extern "C" void kernel_launch(void* const* d_in, const int* in_sizes, int n_in,
                              void* d_out, int out_size) {
    const float* x  = (const float*)d_in[0];   // [N,128]
    const int*   ei = (const int*)  d_in[1];   // [2,E]
    const float* W1 = (const float*)d_in[2];   // [128,64]
    const float* W2 = (const float*)d_in[3];   // [64,40]
    float* out = (float*)d_out;

    int E = in_sizes[1] / 2;
    const int* src = ei;
    const int* dst = ei + E;

    // 1. zero deg
    zero_kernel<<<(NN + 255) / 256, 256>>>();
    // 2. degree histogram (4 edges/thread)
    deg_kernel<<<(E/4 + 255) / 256, 256>>>(dst, E);
    // 3. h1s = (x @ W1) * rsqrt(deg+1)  (register-pipelined; seeds agg1)
    gemm1_kernel<<<(NN + 127) / 128, 256>>>(x, W1);
    // 4. layer-1 edge scatter (split-half lines)  <-- profiled launch
    scatter1_kernel<<<(E * 8 + 255) / 256, 256>>>(src, dst, E);
    // 5. relu + GEMM2 -> h2s; agg2 seeded with self term
    fuse2_kernel<<<(NN + 255) / 256, 256>>>(W2);
    // 6. layer-2 edge scatter (split-half)
    scatter2_kernel<<<(E * 5 + 255) / 256, 256>>>(src, dst, E);
    // 7. final relu -> d_out
    final_kernel<<<(NN * (F2/4) + 255) / 256, 256>>>(out);
}

// round 17
// speedup vs baseline: 1.0833x; 1.0577x over previous
#include <cuda_runtime.h>
#include <cuda_fp16.h>
#include <stdint.h>

// Problem constants (fixed by the dataset)
#define NN 100000      // nodes
#define F0 128
#define F1 64
#define F2 40

// ---------------- scratch (static device globals; allocation-free) ----------
// fp16 transport copies (permuted split-half layout; see scatter kernels):
//   h1h row: halves[8c..8c+3] = float4 chunk c, halves[8c+4..8c+7] = chunk c+8
//   h2h row: halves[8c..8c+3] = float4 chunk c, halves[8c+4..8c+7] = chunk c+5
__device__ __align__(16) __half g_h1h [NN * F1];  // 12.8 MB
__device__ __align__(16) __half g_h2h [NN * F2];  // 8 MB
__device__ __align__(16) float g_agg1[NN * F1];   // fp32: h1s[d] + sum h1s[src]
__device__ __align__(16) float g_agg2[NN * F2];   // fp32: h2s[d] + sum h2s[src]
__device__ int   g_deg[NN];

// ---------------- helpers ---------------------------------------------------
__device__ __forceinline__ void red_add_v4(float* addr, float4 v) {
    asm volatile("red.global.add.v4.f32 [%0], {%1, %2, %3, %4};"
                 :: "l"(addr), "f"(v.x), "f"(v.y), "f"(v.z), "f"(v.w)
                 : "memory");
}
__device__ __forceinline__ float inv_sqrt_deg(int node) {
    return rsqrtf((float)(g_deg[node] + 1));
}
// pack a float4 into 4 fp16 (rn) as uint2
__device__ __forceinline__ uint2 pack_half4(float4 v) {
    union { __half2 h[2]; uint2 u; } pk;
    pk.h[0] = __floats2half2_rn(v.x, v.y);
    pk.h[1] = __floats2half2_rn(v.z, v.w);
    return pk.u;
}
// unpack 4 halves (as uint2) to float4
__device__ __forceinline__ float4 unpack_half4(uint2 u) {
    union { uint2 uu; __half2 h[2]; } pk;
    pk.uu = u;
    float2 a = __half22float2(pk.h[0]);
    float2 b = __half22float2(pk.h[1]);
    return make_float4(a.x, a.y, b.x, b.y);
}

// ---------------- kernels ---------------------------------------------------

// 1st launch: zero deg counters.
__global__ void zero_kernel() {
    int i = blockIdx.x * blockDim.x + threadIdx.x;
    if (i < NN) g_deg[i] = 0;
}

// 2nd launch: degree histogram over dst; 4 edges per thread.
__global__ void deg_kernel(const int* __restrict__ dst, int E) {
    int i = (blockIdx.x * blockDim.x + threadIdx.x) * 4;
    if (i + 3 < E) {
        int4 d = *reinterpret_cast<const int4*>(dst + i);
        atomicAdd(&g_deg[d.x], 1);
        atomicAdd(&g_deg[d.y], 1);
        atomicAdd(&g_deg[d.z], 1);
        atomicAdd(&g_deg[d.w], 1);
    } else {
        for (; i < E; ++i) atomicAdd(&g_deg[dst[i]], 1);
    }
}

// 3rd launch: h1s = (x @ W1) * rsqrt(deg+1)  (8x4 micro-tile, verified).
// Epilogue: seeds agg1 with fp32 h1s (exact self term) and writes fp16
// transport copy h1h in permuted split-half layout.
__global__ __launch_bounds__(256) void gemm1_kernel(const float* __restrict__ x,
                                                    const float* __restrict__ W1) {
    __shared__ float sX[32][132];           // [k_local][row 0..127], padded pitch
    __shared__ float sW[32 * F1];           // [k_local][col], 8 KB
    int tid = threadIdx.x;
    int row0 = blockIdx.x * 128;

    int tx = tid & 15;                      // col group: float4 chunk tx (cols tx*4..+3)
    int ty = tid >> 4;                      // row groups: ty*4 and 64+ty*4

    float acc[8][4];
    #pragma unroll
    for (int r = 0; r < 8; ++r)
        #pragma unroll
        for (int c = 0; c < 4; ++c) acc[r][c] = 0.f;

    #pragma unroll
    for (int kc = 0; kc < 4; ++kc) {
        int k0 = kc * 32;

        const float4* w4g = reinterpret_cast<const float4*>(W1 + k0 * F1);
        #pragma unroll
        for (int i = 0; i < 2; ++i)
            reinterpret_cast<float4*>(sW)[tid + i * 256] = w4g[tid + i * 256];

        #pragma unroll
        for (int i = 0; i < 4; ++i) {
            int idx = tid + i * 256;        // 0..1023
            int r   = idx >> 3;             // 0..127
            int k4  = idx & 7;              // float4 along k
            int rr = row0 + r; if (rr >= NN) rr = NN - 1;
            float4 v = reinterpret_cast<const float4*>(
                           x + (size_t)rr * F0 + k0)[k4];
            sX[k4 * 4 + 0][r] = v.x;
            sX[k4 * 4 + 1][r] = v.y;
            sX[k4 * 4 + 2][r] = v.z;
            sX[k4 * 4 + 3][r] = v.w;
        }
        __syncthreads();

        #pragma unroll 4
        for (int k = 0; k < 32; ++k) {
            float4 xv0 = *reinterpret_cast<const float4*>(&sX[k][ty * 4]);
            float4 xv1 = *reinterpret_cast<const float4*>(&sX[k][64 + ty * 4]);
            float4 wv  = *reinterpret_cast<const float4*>(&sW[k * F1 + tx * 4]);
            float xa[8] = {xv0.x, xv0.y, xv0.z, xv0.w, xv1.x, xv1.y, xv1.z, xv1.w};
            float wa[4] = {wv.x, wv.y, wv.z, wv.w};
            #pragma unroll
            for (int r = 0; r < 8; ++r)
                #pragma unroll
                for (int c = 0; c < 4; ++c)
                    acc[r][c] = fmaf(xa[r], wa[c], acc[r][c]);
        }
        __syncthreads();
    }

    #pragma unroll
    for (int r = 0; r < 8; ++r) {
        int rr = row0 + ((r < 4) ? (ty * 4 + r) : (64 + ty * 4 + r - 4));
        if (rr < NN) {
            float sc = inv_sqrt_deg(rr);
            float4 hv = make_float4(acc[r][0]*sc, acc[r][1]*sc,
                                    acc[r][2]*sc, acc[r][3]*sc);
            // fp32 self-term seed
            *reinterpret_cast<float4*>(g_agg1 + (size_t)rr * F1 + tx * 4) = hv;
            // fp16 transport, permuted: chunk tx<8 at halves 8*tx;
            // chunk tx>=8 at halves 8*(tx-8)+4
            int hoff = (tx < 8) ? (8 * tx) : (8 * (tx - 8) + 4);
            *reinterpret_cast<uint2*>(g_h1h + (size_t)rr * F1 + hoff) = pack_half4(hv);
        }
    }
}

// 4th launch (PROFILED): layer-1 scatter agg1[dst] += h1h[src] (fp16 gather,
// fp32 RED). 8 threads/edge; thread c loads ONE uint4 (16B) covering float4
// chunks c and c+8 (permuted layout) -> gather touches exactly 1 cache line
// per edge (fp16 row = 128B). REDs keep the split-half fp32 pattern.
__global__ __launch_bounds__(256) void scatter1_kernel(const int* __restrict__ src,
                                                       const int* __restrict__ dst, int E) {
    int i = blockIdx.x * blockDim.x + threadIdx.x;
    int total = E * 8;
    if (i >= total) return;
    int e = i >> 3;
    int c = i & 7;
    int s = __ldg(src + e);
    int d = __ldg(dst + e);
    uint4 raw = *reinterpret_cast<const uint4*>(g_h1h + (size_t)s * F1 + c * 8);
    float4 v0 = unpack_half4(make_uint2(raw.x, raw.y));   // chunk c
    float4 v1 = unpack_half4(make_uint2(raw.z, raw.w));   // chunk c+8
    float* ap = g_agg1 + (size_t)d * F1 + c * 4;
    red_add_v4(ap,      v0);
    red_add_v4(ap + 32, v1);
}

// out1 = relu(inv_d * agg1)  (agg1 includes self term).
// h2s = (out1 @ W2) * inv_d; epilogue seeds agg2 (fp32) and writes fp16
// transport h2h in permuted layout (chunks c / c+5).
__global__ __launch_bounds__(256) void fuse2_kernel(const float* __restrict__ W2) {
    __shared__ float sW[F1 * F2];
    int tid = threadIdx.x;
    for (int i = tid; i < F1 * F2; i += 256) sW[i] = W2[i];
    __syncthreads();

    int row = blockIdx.x * 256 + tid;
    if (row >= NN) return;

    float inv_d = inv_sqrt_deg(row);

    float o[F1];
    const float4* ag = reinterpret_cast<const float4*>(g_agg1 + (size_t)row * F1);
    #pragma unroll
    for (int j = 0; j < F1 / 4; ++j) {
        float4 a = ag[j];
        o[4*j+0] = fmaxf(inv_d * a.x, 0.f);
        o[4*j+1] = fmaxf(inv_d * a.y, 0.f);
        o[4*j+2] = fmaxf(inv_d * a.z, 0.f);
        o[4*j+3] = fmaxf(inv_d * a.w, 0.f);
    }

    float acc[F2];
    #pragma unroll
    for (int j = 0; j < F2; ++j) acc[j] = 0.f;

    #pragma unroll 4
    for (int k = 0; k < F1; ++k) {
        float ov = o[k];
        const float4* w4 = reinterpret_cast<const float4*>(sW + k * F2);
        #pragma unroll
        for (int j = 0; j < F2 / 4; ++j) {
            float4 w = w4[j];
            acc[4*j+0] = fmaf(ov, w.x, acc[4*j+0]);
            acc[4*j+1] = fmaf(ov, w.y, acc[4*j+1]);
            acc[4*j+2] = fmaf(ov, w.z, acc[4*j+2]);
            acc[4*j+3] = fmaf(ov, w.w, acc[4*j+3]);
        }
    }
    float4* az = reinterpret_cast<float4*>(g_agg2 + (size_t)row * F2);
    __half* hb = g_h2h + (size_t)row * F2;
    #pragma unroll
    for (int j = 0; j < F2 / 4; ++j) {
        float4 hv = make_float4(acc[4*j]*inv_d, acc[4*j+1]*inv_d,
                                acc[4*j+2]*inv_d, acc[4*j+3]*inv_d);
        az[j] = hv;                         // fp32 self-term seed
        int hoff = (j < 5) ? (8 * j) : (8 * (j - 5) + 4);
        *reinterpret_cast<uint2*>(hb + hoff) = pack_half4(hv);
    }
}

// Layer-2 scatter: agg2[dst] += h2h[src] (fp16 gather, fp32 RED).
// 5 threads/edge; thread c loads one uint4 covering chunks c and c+5
// (permuted layout; fp16 row = 80B, one 16B load per thread).
__global__ __launch_bounds__(256) void scatter2_kernel(const int* __restrict__ src,
                                                       const int* __restrict__ dst, int E) {
    int i = blockIdx.x * blockDim.x + threadIdx.x;
    int total = E * 5;
    if (i >= total) return;
    int e = i / 5;
    int c = i - e * 5;             // 0..4
    int s = __ldg(src + e);
    int d = __ldg(dst + e);
    uint4 raw = *reinterpret_cast<const uint4*>(g_h2h + (size_t)s * F2 + c * 8);
    float4 v0 = unpack_half4(make_uint2(raw.x, raw.y));   // chunk c
    float4 v1 = unpack_half4(make_uint2(raw.z, raw.w));   // chunk c+5
    float* ap = g_agg2 + (size_t)d * F2 + c * 4;
    red_add_v4(ap,      v0);
    red_add_v4(ap + 20, v1);
}

// out = relu(inv_d * agg2)  (agg2 already includes self term)
__global__ __launch_bounds__(256) void final_kernel(float* __restrict__ out) {
    int i = blockIdx.x * blockDim.x + threadIdx.x;
    const int total = NN * (F2 / 4);
    if (i >= total) return;
    int node = i / 10;
    float inv_d = inv_sqrt_deg(node);
    float4 a = reinterpret_cast<const float4*>(g_agg2)[i];
    float4 r;
    r.x = fmaxf(inv_d * a.x, 0.f);
    r.y = fmaxf(inv_d * a.y, 0.f);
    r.z = fmaxf(inv_d * a.z, 0.f);
    r.w = fmaxf(inv_d * a.w, 0.f);
    reinterpret_cast<float4*>(out)[i] = r;
}

// ---------------- launch ----------------------------------------------------
extern "C" void kernel_launch(void* const* d_in, const int* in_sizes, int n_in,
                              void* d_out, int out_size) {
    const float* x  = (const float*)d_in[0];   // [N,128]
    const int*   ei = (const int*)  d_in[1];   // [2,E]
    const float* W1 = (const float*)d_in[2];   // [128,64]
    const float* W2 = (const float*)d_in[3];   // [64,40]
    float* out = (float*)d_out;

    int E = in_sizes[1] / 2;
    const int* src = ei;
    const int* dst = ei + E;

    // 1. zero deg
    zero_kernel<<<(NN + 255) / 256, 256>>>();
    // 2. degree histogram (4 edges/thread)
    deg_kernel<<<(E/4 + 255) / 256, 256>>>(dst, E);
    // 3. gemm1: seeds agg1 (fp32) + fp16 transport h1h
    gemm1_kernel<<<(NN + 127) / 128, 256>>>(x, W1);
    // 4. layer-1 scatter (fp16 gather, fp32 RED)  <-- profiled launch
    scatter1_kernel<<<(E * 8 + 255) / 256, 256>>>(src, dst, E);
    // 5. relu + GEMM2: seeds agg2 (fp32) + fp16 transport h2h
    fuse2_kernel<<<(NN + 255) / 256, 256>>>(W2);
    // 6. layer-2 scatter (fp16 gather, fp32 RED)
    scatter2_kernel<<<(E * 5 + 255) / 256, 256>>>(src, dst, E);
    // 7. final relu -> d_out
    final_kernel<<<(NN * (F2/4) + 255) / 256, 256>>>(out);
}